// round 1
// baseline (speedup 1.0000x reference)
#include <cuda_runtime.h>
#include <math.h>

#define D     128
#define MAXN  8192
#define BM    128
#define PA    132   // smem pitch for A/B tiles (floats)
#define PM    129   // smem pitch for staged mask tile (floats)

__device__ float g_p[(size_t)MAXN * D];
__device__ float g_sq[MAXN];
__device__ float g_negdist[MAXN];
__device__ float g_possum[MAXN];
__device__ float g_cnt[MAXN];

// ---------------------------------------------------------------------------
// Kernel 1: per-row normalize pred & neg, compute sq[i], neg_dist[i],
// zero accumulators (fresh each graph replay).
// ---------------------------------------------------------------------------
__device__ __forceinline__ float bsum128(float v, float* sbuf) {
    #pragma unroll
    for (int o = 16; o > 0; o >>= 1) v += __shfl_down_sync(0xffffffffu, v, o);
    int lane = threadIdx.x & 31, w = threadIdx.x >> 5;
    if (lane == 0) sbuf[w] = v;
    __syncthreads();
    float r = sbuf[0] + sbuf[1] + sbuf[2] + sbuf[3];
    __syncthreads();
    return r;
}

__global__ void k_normalize(const float* __restrict__ pred,
                            const float* __restrict__ neg, int N) {
    __shared__ float sbuf[4];
    int row = blockIdx.x;
    int t = threadIdx.x;
    float pv = pred[(size_t)row * D + t];
    float nv = neg[(size_t)row * D + t];
    float s1 = bsum128(pv * pv, sbuf);
    float s2 = bsum128(nv * nv, sbuf);
    float pn = pv / fmaxf(sqrtf(s1), 1e-12f);
    float nn = nv / fmaxf(sqrtf(s2), 1e-12f);
    g_p[(size_t)row * D + t] = pn;
    float s3 = bsum128(pn * pn, sbuf);
    float d  = pn - nn;
    float s4 = bsum128(d * d, sbuf);
    if (t == 0) {
        g_sq[row]      = s3;
        g_negdist[row] = (s4 > 0.f) ? sqrtf(s4) : 0.f;
        g_possum[row]  = 0.f;
        g_cnt[row]     = 0.f;
    }
}

// ---------------------------------------------------------------------------
// Kernel 2: upper-triangular 128x128 tiles of the gram matrix.
// dist(i,j) symmetric -> each off-diag tile serves both mask[i][j] and
// mask[j][i]. 256 threads, 8x8 micro-tile each, full K=128 smem-resident.
// ---------------------------------------------------------------------------
__global__ __launch_bounds__(256, 1) void k_gram(const float* __restrict__ mask,
                                                 int N) {
    int bi = blockIdx.x, bj = blockIdx.y;
    if (bj < bi) return;                     // upper triangle only
    int I = bi * BM, J = bj * BM;

    extern __shared__ float smem[];
    float*  sA  = smem;                      // [k][i], pitch PA
    float*  sB  = smem + BM * PA;            // [k][j], pitch PA
    float*  sM  = smem;                      // reused: mask[J..][I..], pitch PM
    float2* red = (float2*)(smem + BM * PA); // reused reduction buffer [128][16]

    int tid = threadIdx.x;
    int tx = tid & 15, ty = tid >> 4;

    // Load tiles transposed into smem: s[k][row]
    {
        const float4* Pa = (const float4*)g_p + (size_t)I * (D / 4);
        const float4* Pb = (const float4*)g_p + (size_t)J * (D / 4);
        for (int t = tid; t < BM * (D / 4); t += 256) {
            int r  = t & (BM - 1);
            int c4 = t >> 7;
            float4 va = Pa[(size_t)r * (D / 4) + c4];
            sA[(4 * c4 + 0) * PA + r] = va.x;
            sA[(4 * c4 + 1) * PA + r] = va.y;
            sA[(4 * c4 + 2) * PA + r] = va.z;
            sA[(4 * c4 + 3) * PA + r] = va.w;
            float4 vb = Pb[(size_t)r * (D / 4) + c4];
            sB[(4 * c4 + 0) * PA + r] = vb.x;
            sB[(4 * c4 + 1) * PA + r] = vb.y;
            sB[(4 * c4 + 2) * PA + r] = vb.z;
            sB[(4 * c4 + 3) * PA + r] = vb.w;
        }
    }
    __syncthreads();

    float acc[8][8];
    #pragma unroll
    for (int r = 0; r < 8; r++)
        #pragma unroll
        for (int c = 0; c < 8; c++) acc[r][c] = 0.f;

    #pragma unroll 4
    for (int k = 0; k < D; k++) {
        float4 a0 = *(const float4*)(sA + k * PA + ty * 8);
        float4 a1 = *(const float4*)(sA + k * PA + ty * 8 + 4);
        float4 b0 = *(const float4*)(sB + k * PA + tx * 8);
        float4 b1 = *(const float4*)(sB + k * PA + tx * 8 + 4);
        float a[8] = {a0.x, a0.y, a0.z, a0.w, a1.x, a1.y, a1.z, a1.w};
        float b[8] = {b0.x, b0.y, b0.z, b0.w, b1.x, b1.y, b1.z, b1.w};
        #pragma unroll
        for (int r = 0; r < 8; r++)
            #pragma unroll
            for (int c = 0; c < 8; c++) acc[r][c] += a[r] * b[c];
    }
    __syncthreads();   // done with sA/sB -> safe to reuse regions below

    // convert dot -> dist in place
    float sqi[8], sqj[8];
    #pragma unroll
    for (int r = 0; r < 8; r++) sqi[r] = g_sq[I + ty * 8 + r];
    #pragma unroll
    for (int c = 0; c < 8; c++) sqj[c] = g_sq[J + tx * 8 + c];
    #pragma unroll
    for (int r = 0; r < 8; r++)
        #pragma unroll
        for (int c = 0; c < 8; c++) {
            float d2 = sqi[r] + sqj[c] - 2.f * acc[r][c];
            acc[r][c] = sqrtf(fmaxf(d2, 0.f));
        }

    // ---- pass A: rows I.., mask[I+r][J+c], coalesced direct reads ----
    float psA[8], ctA[8];
    #pragma unroll
    for (int r = 0; r < 8; r++) {
        const float4* mrow =
            (const float4*)(mask + (size_t)(I + ty * 8 + r) * N + J);
        float4 m0 = mrow[2 * tx];
        float4 m1 = mrow[2 * tx + 1];
        psA[r] = acc[r][0] * m0.x + acc[r][1] * m0.y + acc[r][2] * m0.z +
                 acc[r][3] * m0.w + acc[r][4] * m1.x + acc[r][5] * m1.y +
                 acc[r][6] * m1.z + acc[r][7] * m1.w;
        ctA[r] = m0.x + m0.y + m0.z + m0.w + m1.x + m1.y + m1.z + m1.w;
    }
    #pragma unroll
    for (int r = 0; r < 8; r++)
        red[(ty * 8 + r) * 16 + tx] = make_float2(psA[r], ctA[r]);
    __syncthreads();
    if (tid < BM) {
        float s = 0.f, c = 0.f;
        #pragma unroll
        for (int t2 = 0; t2 < 16; t2++) {
            float2 v = red[tid * 16 + t2];
            s += v.x; c += v.y;
        }
        atomicAdd(&g_possum[I + tid], s);
        atomicAdd(&g_cnt[I + tid], c);
    }

    // ---- pass B (off-diag only): rows J.., mask[J+c][I+r], staged ----
    if (bi != bj) {
        // stage mask[J..J+127][I..I+127] into sM[jr*PM + ic] (coalesced)
        const float* mB = mask + (size_t)J * N + I;
        for (int t2 = tid; t2 < BM * (BM / 4); t2 += 256) {
            int jr = t2 >> 5;
            int c4 = t2 & 31;
            float4 v = *(const float4*)(mB + (size_t)jr * N + c4 * 4);
            sM[jr * PM + 4 * c4 + 0] = v.x;
            sM[jr * PM + 4 * c4 + 1] = v.y;
            sM[jr * PM + 4 * c4 + 2] = v.z;
            sM[jr * PM + 4 * c4 + 3] = v.w;
        }
        __syncthreads();

        float psB[8], ctB[8];
        #pragma unroll
        for (int c = 0; c < 8; c++) { psB[c] = 0.f; ctB[c] = 0.f; }
        #pragma unroll
        for (int r = 0; r < 8; r++)
            #pragma unroll
            for (int c = 0; c < 8; c++) {
                float m = sM[(tx * 8 + c) * PM + ty * 8 + r];
                psB[c] += acc[r][c] * m;
                ctB[c] += m;
            }
        #pragma unroll
        for (int c = 0; c < 8; c++)
            red[(tx * 8 + c) * 16 + ty] = make_float2(psB[c], ctB[c]);
        __syncthreads();
        if (tid < BM) {
            float s = 0.f, c = 0.f;
            #pragma unroll
            for (int t2 = 0; t2 < 16; t2++) {
                float2 v = red[tid * 16 + t2];
                s += v.x; c += v.y;
            }
            atomicAdd(&g_possum[J + tid], s);
            atomicAdd(&g_cnt[J + tid], c);
        }
    }
}

// ---------------------------------------------------------------------------
// Kernel 3: final scalar mean
// ---------------------------------------------------------------------------
__global__ void k_final(float* __restrict__ out, int N) {
    __shared__ float sb[32];
    float s = 0.f;
    for (int i = threadIdx.x; i < N; i += blockDim.x)
        s += g_possum[i] / fmaxf(g_cnt[i], 1.f) - g_negdist[i];
    #pragma unroll
    for (int o = 16; o > 0; o >>= 1) s += __shfl_down_sync(0xffffffffu, s, o);
    int lane = threadIdx.x & 31, w = threadIdx.x >> 5;
    if (lane == 0) sb[w] = s;
    __syncthreads();
    if (w == 0) {
        float r = (lane < (int)(blockDim.x >> 5)) ? sb[lane] : 0.f;
        #pragma unroll
        for (int o = 16; o > 0; o >>= 1) r += __shfl_down_sync(0xffffffffu, r, o);
        if (lane == 0) out[0] = r / (float)N;
    }
}

// ---------------------------------------------------------------------------
extern "C" void kernel_launch(void* const* d_in, const int* in_sizes, int n_in,
                              void* d_out, int out_size) {
    const float* pred = (const float*)d_in[0];
    const float* mask = (const float*)d_in[1];
    const float* neg  = (const float*)d_in[2];
    int N = in_sizes[0] / D;

    k_normalize<<<N, 128>>>(pred, neg, N);

    int nb = N / BM;
    size_t smem = (size_t)(2 * BM * PA) * sizeof(float);
    cudaFuncSetAttribute(k_gram, cudaFuncAttributeMaxDynamicSharedMemorySize,
                         (int)smem);
    dim3 grid(nb, nb);
    k_gram<<<grid, 256, smem>>>(mask, N);

    k_final<<<1, 1024>>>((float*)d_out, N);
}

// round 3
// speedup vs baseline: 1.6862x; 1.6862x over previous
#include <cuda_runtime.h>
#include <cuda_bf16.h>
#include <math.h>
#include <stdint.h>

#define D      128
#define MAXN   8192
#define BM     128
#define NTILES (MAXN / BM)
#define PITCHB 272          // smem tile pitch in bytes (136 bf16)
#define TILEB  (128 * PITCHB) // 34816 bytes per staged tile
#define PT     129          // dist tile pitch (floats) -> conflict-free rows & cols

__device__ float g_sq[MAXN];
__device__ float g_negdist[MAXN];
__device__ float g_possum[MAXN];
__device__ float g_cnt[MAXN];
__device__ __nv_bfloat16 g_hi[(size_t)MAXN * D];
__device__ __nv_bfloat16 g_lo[(size_t)MAXN * D];

// ---------------- helpers ----------------
__device__ __forceinline__ uint32_t smem_u32(const void* p) {
    uint32_t a;
    asm("{ .reg .u64 t; cvta.to.shared.u64 t, %1; cvt.u32.u64 %0, t; }"
        : "=r"(a) : "l"(p));
    return a;
}

__device__ __forceinline__ void ldm_x4(uint32_t* r, uint32_t addr) {
    asm volatile("ldmatrix.sync.aligned.m8n8.x4.shared.b16 {%0,%1,%2,%3}, [%4];"
                 : "=r"(r[0]), "=r"(r[1]), "=r"(r[2]), "=r"(r[3]) : "r"(addr));
}

__device__ __forceinline__ void mma_bf16(float* c, const uint32_t* a,
                                         uint32_t b0, uint32_t b1) {
    asm volatile(
        "mma.sync.aligned.m16n8k16.row.col.f32.bf16.bf16.f32 "
        "{%0,%1,%2,%3}, {%4,%5,%6,%7}, {%8,%9}, {%0,%1,%2,%3};"
        : "+f"(c[0]), "+f"(c[1]), "+f"(c[2]), "+f"(c[3])
        : "r"(a[0]), "r"(a[1]), "r"(a[2]), "r"(a[3]), "r"(b0), "r"(b1));
}

// ---------------------------------------------------------------------------
// Kernel 1: normalize, sq, neg_dist, zero accumulators, emit hi/lo bf16 rows
// ---------------------------------------------------------------------------
__device__ __forceinline__ float bsum128(float v, float* sbuf) {
    #pragma unroll
    for (int o = 16; o > 0; o >>= 1) v += __shfl_down_sync(0xffffffffu, v, o);
    int lane = threadIdx.x & 31, w = threadIdx.x >> 5;
    if (lane == 0) sbuf[w] = v;
    __syncthreads();
    float r = sbuf[0] + sbuf[1] + sbuf[2] + sbuf[3];
    __syncthreads();
    return r;
}

__global__ void k_normalize(const float* __restrict__ pred,
                            const float* __restrict__ neg, int N) {
    __shared__ float sbuf[4];
    int row = blockIdx.x;
    int t = threadIdx.x;
    float pv = pred[(size_t)row * D + t];
    float nv = neg[(size_t)row * D + t];
    float s1 = bsum128(pv * pv, sbuf);
    float s2 = bsum128(nv * nv, sbuf);
    float pn = pv / fmaxf(sqrtf(s1), 1e-12f);
    float nn = nv / fmaxf(sqrtf(s2), 1e-12f);
    float s3 = bsum128(pn * pn, sbuf);
    float d  = pn - nn;
    float s4 = bsum128(d * d, sbuf);

    __nv_bfloat16 hi = __float2bfloat16(pn);
    __nv_bfloat16 lo = __float2bfloat16(pn - __bfloat162float(hi));
    g_hi[(size_t)row * D + t] = hi;
    g_lo[(size_t)row * D + t] = lo;

    if (t == 0) {
        g_sq[row]      = s3;
        g_negdist[row] = (s4 > 0.f) ? sqrtf(s4) : 0.f;
        g_possum[row]  = 0.f;
        g_cnt[row]     = 0.f;
    }
}

// ---------------------------------------------------------------------------
// Kernel 2: 128x128 gram tiles (upper triangle) via mma.sync bf16, 3-pass
// hi/lo split (hh + hl + lh), fused dist + mask epilogue for both sides.
// smem: slotA [0,TILEB), slotB [TILEB,2*TILEB), sqi/sqj after; dist tile
// reuses [0, 128*PT*4) after the MMA passes.
// ---------------------------------------------------------------------------
#define OFF_SQI (2 * TILEB)
#define OFF_SQJ (2 * TILEB + 512)
#define SMEM_SZ (2 * TILEB + 1024)

__device__ __forceinline__ void stage_tile(char* smem, uint32_t dst,
                                           const __nv_bfloat16* src) {
    const uint4* s = (const uint4*)src;
    int tid = threadIdx.x;
    #pragma unroll
    for (int t = tid; t < 2048; t += 256) {
        int row = t >> 4, c = t & 15;
        *(uint4*)(smem + dst + row * PITCHB + c * 16) = s[t];
    }
}

__global__ __launch_bounds__(256) void k_gram(const float* __restrict__ mask,
                                              int N) {
    int bi = blockIdx.x, bj = blockIdx.y;
    if (bj < bi) return;
    bool diag = (bi == bj);
    int I = bi * BM, J = bj * BM;

    extern __shared__ char smem[];
    uint32_t sbase = smem_u32(smem);
    float* sdist = (float*)smem;
    float* sqi = (float*)(smem + OFF_SQI);
    float* sqj = (float*)(smem + OFF_SQJ);

    int tid = threadIdx.x, wid = tid >> 5, lane = tid & 31;
    int wr = wid >> 1, wc = wid & 1;       // warp tile: rows wr*32, cols wc*64

    const __nv_bfloat16* Ahi = g_hi + (size_t)I * D;
    const __nv_bfloat16* Alo = g_lo + (size_t)I * D;
    const __nv_bfloat16* Bhi = g_hi + (size_t)J * D;
    const __nv_bfloat16* Blo = g_lo + (size_t)J * D;

    if (tid < 128) sqi[tid] = g_sq[I + tid];
    else sqj[tid - 128] = g_sq[J + tid - 128];

    float acc[2][8][4];
    #pragma unroll
    for (int mi = 0; mi < 2; mi++)
        #pragma unroll
        for (int ni = 0; ni < 8; ni++)
            #pragma unroll
            for (int q = 0; q < 4; q++) acc[mi][ni][q] = 0.f;

    // per-lane ldmatrix base offsets
    uint32_t aAddr0 = sbase + (uint32_t)((wr * 32 + (lane & 15)) * PITCHB +
                                         (lane >> 4) * 16);
    uint32_t bAddr0 = sbase + TILEB +
                      (uint32_t)((wc * 64 + (lane & 15)) * PITCHB +
                                 (lane >> 4) * 16);

    #pragma unroll 1
    for (int pass = 0; pass < 3; pass++) {
        __syncthreads();
        if (pass == 0) {
            stage_tile(smem, 0, Ahi);
            stage_tile(smem, TILEB, Bhi);
        } else if (pass == 1) {
            stage_tile(smem, TILEB, Blo);      // (Ah, Bl)
        } else {
            stage_tile(smem, 0, Alo);          // (Al, Bh)
            stage_tile(smem, TILEB, Bhi);
        }
        __syncthreads();

        #pragma unroll
        for (int ks = 0; ks < 8; ks++) {
            uint32_t a[2][4];
            ldm_x4(a[0], aAddr0 + ks * 32);
            ldm_x4(a[1], aAddr0 + ks * 32 + 16 * PITCHB);
            uint32_t b[4][4];
            #pragma unroll
            for (int n2 = 0; n2 < 4; n2++)
                ldm_x4(b[n2], bAddr0 + ks * 32 + n2 * 16 * PITCHB);
            #pragma unroll
            for (int mi = 0; mi < 2; mi++)
                #pragma unroll
                for (int ni = 0; ni < 8; ni++)
                    mma_bf16(acc[mi][ni], a[mi],
                             b[ni >> 1][ni & 1], b[ni >> 1][(ni & 1) + 2]);
        }
    }
    __syncthreads();

    // dot -> dist, write dist tile to smem (pitch PT)
    #pragma unroll
    for (int mi = 0; mi < 2; mi++) {
        int rbase = wr * 32 + mi * 16 + (lane >> 2);
        #pragma unroll
        for (int ni = 0; ni < 8; ni++) {
            int cbase = wc * 64 + ni * 8 + (lane & 3) * 2;
            #pragma unroll
            for (int q = 0; q < 4; q++) {
                int r = rbase + (q >> 1) * 8;
                int c = cbase + (q & 1);
                float d2 = sqi[r] + sqj[c] - 2.f * acc[mi][ni][q];
                float dv = sqrtf(fmaxf(d2, 0.f));
                if (diag && r == c) dv = 0.f;
                sdist[r * PT + c] = dv;
            }
        }
    }
    __syncthreads();

    // pass A: rows I+r, mask[I+r][J..], coalesced; warp per 16 rows
    #pragma unroll 1
    for (int rr = 0; rr < 16; rr++) {
        int r = wid * 16 + rr;
        const float* mrow = mask + (size_t)(I + r) * N + J;
        float ps = 0.f, ct = 0.f;
        #pragma unroll
        for (int q = 0; q < 4; q++) {
            float m = mrow[q * 32 + lane];
            float dv = sdist[r * PT + q * 32 + lane];
            ps += m * dv;
            ct += m;
        }
        #pragma unroll
        for (int o = 16; o > 0; o >>= 1) {
            ps += __shfl_down_sync(0xffffffffu, ps, o);
            ct += __shfl_down_sync(0xffffffffu, ct, o);
        }
        if (lane == 0) {
            atomicAdd(&g_possum[I + r], ps);
            atomicAdd(&g_cnt[I + r], ct);
        }
    }

    // pass B (off-diag): cols J+c, mask[J+c][I..], dist column reads
    if (!diag) {
        #pragma unroll 1
        for (int cc = 0; cc < 16; cc++) {
            int c = wid * 16 + cc;
            const float* mrow = mask + (size_t)(J + c) * N + I;
            float ps = 0.f, ct = 0.f;
            #pragma unroll
            for (int q = 0; q < 4; q++) {
                float m = mrow[q * 32 + lane];
                float dv = sdist[(q * 32 + lane) * PT + c];
                ps += m * dv;
                ct += m;
            }
            #pragma unroll
            for (int o = 16; o > 0; o >>= 1) {
                ps += __shfl_down_sync(0xffffffffu, ps, o);
                ct += __shfl_down_sync(0xffffffffu, ct, o);
            }
            if (lane == 0) {
                atomicAdd(&g_possum[J + c], ps);
                atomicAdd(&g_cnt[J + c], ct);
            }
        }
    }
}

// ---------------------------------------------------------------------------
// Kernel 3: final scalar mean
// ---------------------------------------------------------------------------
__global__ void k_final(float* __restrict__ out, int N) {
    __shared__ float sb[32];
    float s = 0.f;
    for (int i = threadIdx.x; i < N; i += blockDim.x)
        s += g_possum[i] / fmaxf(g_cnt[i], 1.f) - g_negdist[i];
    #pragma unroll
    for (int o = 16; o > 0; o >>= 1) s += __shfl_down_sync(0xffffffffu, s, o);
    int lane = threadIdx.x & 31, w = threadIdx.x >> 5;
    if (lane == 0) sb[w] = s;
    __syncthreads();
    if (w == 0) {
        float r = (lane < (int)(blockDim.x >> 5)) ? sb[lane] : 0.f;
        #pragma unroll
        for (int o = 16; o > 0; o >>= 1) r += __shfl_down_sync(0xffffffffu, r, o);
        if (lane == 0) out[0] = r / (float)N;
    }
}

// ---------------------------------------------------------------------------
extern "C" void kernel_launch(void* const* d_in, const int* in_sizes, int n_in,
                              void* d_out, int out_size) {
    const float* pred = (const float*)d_in[0];
    const float* mask = (const float*)d_in[1];
    const float* neg  = (const float*)d_in[2];
    int N = in_sizes[0] / D;

    k_normalize<<<N, 128>>>(pred, neg, N);

    int nb = N / BM;
    cudaFuncSetAttribute(k_gram, cudaFuncAttributeMaxDynamicSharedMemorySize,
                         SMEM_SZ);
    dim3 grid(nb, nb);
    k_gram<<<grid, 256, SMEM_SZ>>>(mask, N);

    k_final<<<1, 1024>>>((float*)d_out, N);
}

// round 4
// speedup vs baseline: 1.6875x; 1.0007x over previous
#include <cuda_runtime.h>
#include <cuda_bf16.h>
#include <math.h>
#include <stdint.h>

#define D      128
#define MAXN   8192
#define BM     128
#define NTILES (MAXN / BM)
#define PITCHB 272          // smem tile pitch in bytes (136 bf16)
#define TILEB  (128 * PITCHB) // 34816 bytes per staged tile
#define PT     129          // dist tile pitch (floats) -> conflict-free rows & cols

__device__ float g_sq[MAXN];
__device__ float g_negdist[MAXN];
__device__ float g_possum[MAXN];
__device__ float g_cnt[MAXN];
__device__ __nv_bfloat16 g_hi[(size_t)MAXN * D];
__device__ __nv_bfloat16 g_lo[(size_t)MAXN * D];

// ---------------- helpers ----------------
__device__ __forceinline__ uint32_t smem_u32(const void* p) {
    uint32_t a;
    asm("{ .reg .u64 t; cvta.to.shared.u64 t, %1; cvt.u32.u64 %0, t; }"
        : "=r"(a) : "l"(p));
    return a;
}

__device__ __forceinline__ void ldm_x4(uint32_t* r, uint32_t addr) {
    asm volatile("ldmatrix.sync.aligned.m8n8.x4.shared.b16 {%0,%1,%2,%3}, [%4];"
                 : "=r"(r[0]), "=r"(r[1]), "=r"(r[2]), "=r"(r[3]) : "r"(addr));
}

__device__ __forceinline__ void mma_bf16(float* c, const uint32_t* a,
                                         uint32_t b0, uint32_t b1) {
    asm volatile(
        "mma.sync.aligned.m16n8k16.row.col.f32.bf16.bf16.f32 "
        "{%0,%1,%2,%3}, {%4,%5,%6,%7}, {%8,%9}, {%0,%1,%2,%3};"
        : "+f"(c[0]), "+f"(c[1]), "+f"(c[2]), "+f"(c[3])
        : "r"(a[0]), "r"(a[1]), "r"(a[2]), "r"(a[3]), "r"(b0), "r"(b1));
}

// ---------------------------------------------------------------------------
// Kernel 1: normalize, sq, neg_dist, zero accumulators, emit hi/lo bf16 rows
// ---------------------------------------------------------------------------
__device__ __forceinline__ float bsum128(float v, float* sbuf) {
    #pragma unroll
    for (int o = 16; o > 0; o >>= 1) v += __shfl_down_sync(0xffffffffu, v, o);
    int lane = threadIdx.x & 31, w = threadIdx.x >> 5;
    if (lane == 0) sbuf[w] = v;
    __syncthreads();
    float r = sbuf[0] + sbuf[1] + sbuf[2] + sbuf[3];
    __syncthreads();
    return r;
}

__global__ void k_normalize(const float* __restrict__ pred,
                            const float* __restrict__ neg, int N) {
    __shared__ float sbuf[4];
    int row = blockIdx.x;
    int t = threadIdx.x;
    float pv = pred[(size_t)row * D + t];
    float nv = neg[(size_t)row * D + t];
    float s1 = bsum128(pv * pv, sbuf);
    float s2 = bsum128(nv * nv, sbuf);
    float pn = pv / fmaxf(sqrtf(s1), 1e-12f);
    float nn = nv / fmaxf(sqrtf(s2), 1e-12f);
    float s3 = bsum128(pn * pn, sbuf);
    float d  = pn - nn;
    float s4 = bsum128(d * d, sbuf);

    __nv_bfloat16 hi = __float2bfloat16(pn);
    __nv_bfloat16 lo = __float2bfloat16(pn - __bfloat162float(hi));
    g_hi[(size_t)row * D + t] = hi;
    g_lo[(size_t)row * D + t] = lo;

    if (t == 0) {
        g_sq[row]      = s3;
        g_negdist[row] = (s4 > 0.f) ? sqrtf(s4) : 0.f;
        g_possum[row]  = 0.f;
        g_cnt[row]     = 0.f;
    }
}

// ---------------------------------------------------------------------------
// Kernel 2: 128x128 gram tiles (upper triangle) via mma.sync bf16, 3-pass
// hi/lo split (hh + hl + lh), fused dist + mask epilogue for both sides.
// smem: slotA [0,TILEB), slotB [TILEB,2*TILEB), sqi/sqj after; dist tile
// reuses [0, 128*PT*4) after the MMA passes.
// ---------------------------------------------------------------------------
#define OFF_SQI (2 * TILEB)
#define OFF_SQJ (2 * TILEB + 512)
#define SMEM_SZ (2 * TILEB + 1024)

__device__ __forceinline__ void stage_tile(char* smem, uint32_t dst,
                                           const __nv_bfloat16* src) {
    const uint4* s = (const uint4*)src;
    int tid = threadIdx.x;
    #pragma unroll
    for (int t = tid; t < 2048; t += 256) {
        int row = t >> 4, c = t & 15;
        *(uint4*)(smem + dst + row * PITCHB + c * 16) = s[t];
    }
}

__global__ __launch_bounds__(256) void k_gram(const float* __restrict__ mask,
                                              int N) {
    int bi = blockIdx.x, bj = blockIdx.y;
    if (bj < bi) return;
    bool diag = (bi == bj);
    int I = bi * BM, J = bj * BM;

    extern __shared__ char smem[];
    uint32_t sbase = smem_u32(smem);
    float* sdist = (float*)smem;
    float* sqi = (float*)(smem + OFF_SQI);
    float* sqj = (float*)(smem + OFF_SQJ);

    int tid = threadIdx.x, wid = tid >> 5, lane = tid & 31;
    int wr = wid >> 1, wc = wid & 1;       // warp tile: rows wr*32, cols wc*64

    const __nv_bfloat16* Ahi = g_hi + (size_t)I * D;
    const __nv_bfloat16* Alo = g_lo + (size_t)I * D;
    const __nv_bfloat16* Bhi = g_hi + (size_t)J * D;
    const __nv_bfloat16* Blo = g_lo + (size_t)J * D;

    if (tid < 128) sqi[tid] = g_sq[I + tid];
    else sqj[tid - 128] = g_sq[J + tid - 128];

    float acc[2][8][4];
    #pragma unroll
    for (int mi = 0; mi < 2; mi++)
        #pragma unroll
        for (int ni = 0; ni < 8; ni++)
            #pragma unroll
            for (int q = 0; q < 4; q++) acc[mi][ni][q] = 0.f;

    // per-lane ldmatrix base offsets
    uint32_t aAddr0 = sbase + (uint32_t)((wr * 32 + (lane & 15)) * PITCHB +
                                         (lane >> 4) * 16);
    uint32_t bAddr0 = sbase + TILEB +
                      (uint32_t)((wc * 64 + (lane & 15)) * PITCHB +
                                 (lane >> 4) * 16);

    #pragma unroll 1
    for (int pass = 0; pass < 3; pass++) {
        __syncthreads();
        if (pass == 0) {
            stage_tile(smem, 0, Ahi);
            stage_tile(smem, TILEB, Bhi);
        } else if (pass == 1) {
            stage_tile(smem, TILEB, Blo);      // (Ah, Bl)
        } else {
            stage_tile(smem, 0, Alo);          // (Al, Bh)
            stage_tile(smem, TILEB, Bhi);
        }
        __syncthreads();

        #pragma unroll
        for (int ks = 0; ks < 8; ks++) {
            uint32_t a[2][4];
            ldm_x4(a[0], aAddr0 + ks * 32);
            ldm_x4(a[1], aAddr0 + ks * 32 + 16 * PITCHB);
            uint32_t b[4][4];
            #pragma unroll
            for (int n2 = 0; n2 < 4; n2++)
                ldm_x4(b[n2], bAddr0 + ks * 32 + n2 * 16 * PITCHB);
            #pragma unroll
            for (int mi = 0; mi < 2; mi++)
                #pragma unroll
                for (int ni = 0; ni < 8; ni++)
                    mma_bf16(acc[mi][ni], a[mi],
                             b[ni >> 1][ni & 1], b[ni >> 1][(ni & 1) + 2]);
        }
    }
    __syncthreads();

    // dot -> dist, write dist tile to smem (pitch PT)
    #pragma unroll
    for (int mi = 0; mi < 2; mi++) {
        int rbase = wr * 32 + mi * 16 + (lane >> 2);
        #pragma unroll
        for (int ni = 0; ni < 8; ni++) {
            int cbase = wc * 64 + ni * 8 + (lane & 3) * 2;
            #pragma unroll
            for (int q = 0; q < 4; q++) {
                int r = rbase + (q >> 1) * 8;
                int c = cbase + (q & 1);
                float d2 = sqi[r] + sqj[c] - 2.f * acc[mi][ni][q];
                float dv = sqrtf(fmaxf(d2, 0.f));
                if (diag && r == c) dv = 0.f;
                sdist[r * PT + c] = dv;
            }
        }
    }
    __syncthreads();

    // pass A: rows I+r, mask[I+r][J..], coalesced; warp per 16 rows
    #pragma unroll 1
    for (int rr = 0; rr < 16; rr++) {
        int r = wid * 16 + rr;
        const float* mrow = mask + (size_t)(I + r) * N + J;
        float ps = 0.f, ct = 0.f;
        #pragma unroll
        for (int q = 0; q < 4; q++) {
            float m = mrow[q * 32 + lane];
            float dv = sdist[r * PT + q * 32 + lane];
            ps += m * dv;
            ct += m;
        }
        #pragma unroll
        for (int o = 16; o > 0; o >>= 1) {
            ps += __shfl_down_sync(0xffffffffu, ps, o);
            ct += __shfl_down_sync(0xffffffffu, ct, o);
        }
        if (lane == 0) {
            atomicAdd(&g_possum[I + r], ps);
            atomicAdd(&g_cnt[I + r], ct);
        }
    }

    // pass B (off-diag): cols J+c, mask[J+c][I..], dist column reads
    if (!diag) {
        #pragma unroll 1
        for (int cc = 0; cc < 16; cc++) {
            int c = wid * 16 + cc;
            const float* mrow = mask + (size_t)(J + c) * N + I;
            float ps = 0.f, ct = 0.f;
            #pragma unroll
            for (int q = 0; q < 4; q++) {
                float m = mrow[q * 32 + lane];
                float dv = sdist[(q * 32 + lane) * PT + c];
                ps += m * dv;
                ct += m;
            }
            #pragma unroll
            for (int o = 16; o > 0; o >>= 1) {
                ps += __shfl_down_sync(0xffffffffu, ps, o);
                ct += __shfl_down_sync(0xffffffffu, ct, o);
            }
            if (lane == 0) {
                atomicAdd(&g_possum[J + c], ps);
                atomicAdd(&g_cnt[J + c], ct);
            }
        }
    }
}

// ---------------------------------------------------------------------------
// Kernel 3: final scalar mean
// ---------------------------------------------------------------------------
__global__ void k_final(float* __restrict__ out, int N) {
    __shared__ float sb[32];
    float s = 0.f;
    for (int i = threadIdx.x; i < N; i += blockDim.x)
        s += g_possum[i] / fmaxf(g_cnt[i], 1.f) - g_negdist[i];
    #pragma unroll
    for (int o = 16; o > 0; o >>= 1) s += __shfl_down_sync(0xffffffffu, s, o);
    int lane = threadIdx.x & 31, w = threadIdx.x >> 5;
    if (lane == 0) sb[w] = s;
    __syncthreads();
    if (w == 0) {
        float r = (lane < (int)(blockDim.x >> 5)) ? sb[lane] : 0.f;
        #pragma unroll
        for (int o = 16; o > 0; o >>= 1) r += __shfl_down_sync(0xffffffffu, r, o);
        if (lane == 0) out[0] = r / (float)N;
    }
}

// ---------------------------------------------------------------------------
extern "C" void kernel_launch(void* const* d_in, const int* in_sizes, int n_in,
                              void* d_out, int out_size) {
    const float* pred = (const float*)d_in[0];
    const float* mask = (const float*)d_in[1];
    const float* neg  = (const float*)d_in[2];
    int N = in_sizes[0] / D;

    k_normalize<<<N, 128>>>(pred, neg, N);

    int nb = N / BM;
    cudaFuncSetAttribute(k_gram, cudaFuncAttributeMaxDynamicSharedMemorySize,
                         SMEM_SZ);
    dim3 grid(nb, nb);
    k_gram<<<grid, 256, SMEM_SZ>>>(mask, N);

    k_final<<<1, 1024>>>((float*)d_out, N);
}